// round 3
// baseline (speedup 1.0000x reference)
#include <cuda_runtime.h>

#define NN 19
#define PP 361
#define BB 16
#define HH 8
#define BPTOT (BB*PP)            // 5776
#define LN_EPS 1e-5f
#define INV_SQRT_HD 0.1767766952966369f   // 1/sqrt(32)

// ---------------- scratch: device globals (no allocations allowed) ----------------
__device__ float d_XQKV[BPTOT*768];                   // [bp][xq|xk|xv]
__device__ float d_YV[(size_t)BPTOT*2048];            // [bp][h][256]
__device__ float d_E2[(size_t)BPTOT*NN*256];          // [bp][n][256]
__device__ float d_Q2[(size_t)BPTOT*2*256];
__device__ float d_K2s[(size_t)BPTOT*8*256];
__device__ float d_V2s[(size_t)BPTOT*8*256];
__device__ float d_ATT2[(size_t)BPTOT*2*256];
__device__ float d_Z2[(size_t)BPTOT*2*256];
__device__ float d_cvec[256];
__device__ int d_deg[NN];
__device__ int d_nbrs[NN][8];
__device__ int d_mcnt[PP];
__device__ int d_mlist[PP][8];
__device__ int d_qdeg[PP][2];
__device__ int d_qslot[PP][2][4];
__device__ int d_rowq[BPTOT*2];
__device__ int d_rowm[BPTOT*8];

// ---------------- table building ----------------
__global__ void k_tables(const float* __restrict__ adj) {
    int t = threadIdx.x;
    if (t < NN) {
        int d = 0;
        for (int m = 0; m < NN; m++)
            if (adj[t*NN + m] > 0.f) d_nbrs[t][d++] = m;
        d_deg[t] = d;                 // max degree is 4
    }
    __syncthreads();
    for (int p = t; p < PP; p += blockDim.x) {
        int i = p / NN, j = p % NN;
        int lst[8]; int cnt = 0;
        for (int s = 0; s < d_deg[i]; s++) lst[cnt++] = d_nbrs[i][s];
        for (int s = 0; s < d_deg[j]; s++) {
            int m = d_nbrs[j][s];
            bool f = false;
            for (int q = 0; q < cnt; q++) if (lst[q] == m) f = true;
            if (!f) lst[cnt++] = m;
        }
        d_mcnt[p] = cnt;
        for (int s = 0; s < 8; s++) d_mlist[p][s] = (s < cnt) ? lst[s] : lst[0];
        int nodes[2] = {i, j};
        for (int tt = 0; tt < 2; tt++) {
            int n = nodes[tt];
            int dg = d_deg[n];
            d_qdeg[p][tt] = dg;
            for (int s = 0; s < 4; s++) {
                int slot = 0;
                if (s < dg) {
                    int m = d_nbrs[n][s];
                    for (int q = 0; q < cnt; q++) if (lst[q] == m) { slot = q; break; }
                }
                d_qslot[p][tt][s] = slot;
            }
        }
    }
}

__global__ void k_rowmaps() {
    int bp = blockIdx.x * blockDim.x + threadIdx.x;
    if (bp >= BPTOT) return;
    int p = bp % PP;
    int i = p / NN, j = p % NN;
    d_rowq[bp*2 + 0] = bp*NN + i;
    d_rowq[bp*2 + 1] = bp*NN + j;
    for (int s = 0; s < 8; s++) d_rowm[bp*8 + s] = bp*NN + d_mlist[p][s];
}

// cvec = bv0 @ Wo0 + bo0
__global__ void k_cvec(const float* __restrict__ bv0, const float* __restrict__ Wo0,
                       const float* __restrict__ bo0) {
    int d = threadIdx.x;
    float acc = bo0[d];
    for (int k = 0; k < 256; k++) acc += bv0[k] * Wo0[k*256 + d];
    d_cvec[d] = acc;
}

// ---------------- generic GEMM: C[M,256] = gather(A)[M,K] @ B[K,256] (+bias) ----------------
__global__ void __launch_bounds__(256) k_gemm(
    const float* __restrict__ A, int lda,
    const int* __restrict__ rowmap,
    const float* __restrict__ B,
    const float* __restrict__ bias,
    float* __restrict__ C, int ldc,
    int M, int K)
{
    __shared__ float As[16][132];
    __shared__ float Bs[16][128];
    __shared__ int rmap[128];
    int row0 = blockIdx.x * 128;
    int col0 = blockIdx.y * 128;
    int tid = threadIdx.x;
    int tx = tid & 15, ty = tid >> 4;

    for (int r = tid; r < 128; r += 256) {
        int gr = row0 + r;
        rmap[r] = (gr < M) ? (rowmap ? rowmap[gr] : gr) : 0;
    }
    __syncthreads();

    float acc[8][8];
#pragma unroll
    for (int i = 0; i < 8; i++)
#pragma unroll
        for (int j = 0; j < 8; j++) acc[i][j] = 0.f;

    // B staging indices: 256 threads x 2 float4 = 2048 floats = 16x128
    int bc4 = (tid & 31) * 4;        // 0..124, float4 column within 128
    int bk0 = tid >> 5;              // 0..7, k row; rows bk0 and bk0+8

    for (int k0 = 0; k0 < K; k0 += 16) {
#pragma unroll
        for (int t = 0; t < 8; t++) {
            int l = tid + t * 256;
            int r = l >> 4, kk = l & 15;
            As[kk][r] = A[(size_t)rmap[r] * lda + k0 + kk];
        }
        {
            float4 b0 = *(const float4*)&B[(size_t)(k0 + bk0) * 256 + col0 + bc4];
            float4 b1 = *(const float4*)&B[(size_t)(k0 + bk0 + 8) * 256 + col0 + bc4];
            *(float4*)&Bs[bk0][bc4]     = b0;
            *(float4*)&Bs[bk0 + 8][bc4] = b1;
        }
        __syncthreads();
#pragma unroll
        for (int kk = 0; kk < 16; kk++) {
            float a[8], b[8];
#pragma unroll
            for (int i = 0; i < 8; i++) a[i] = As[kk][ty + i*16];
#pragma unroll
            for (int j = 0; j < 8; j++) b[j] = Bs[kk][tx + j*16];
#pragma unroll
            for (int i = 0; i < 8; i++)
#pragma unroll
                for (int j = 0; j < 8; j++) acc[i][j] += a[i] * b[j];
        }
        __syncthreads();
    }
#pragma unroll
    for (int i = 0; i < 8; i++) {
        int gr = row0 + ty + i*16;
        if (gr >= M) continue;
#pragma unroll
        for (int j = 0; j < 8; j++) {
            int gc = col0 + tx + j*16;
            float v = acc[i][j];
            if (bias) v += __ldg(&bias[gc]);
            C[(size_t)gr * ldc + gc] = v;
        }
    }
}

// ---------------- layer-1 attention (collapsed) + E2 build + LN ----------------
__global__ void __launch_bounds__(256) k_attn1(
    const float* __restrict__ x,
    const float* __restrict__ bq0, const float* __restrict__ bk0,
    const float* __restrict__ g0, const float* __restrict__ b0)
{
    int bp = blockIdx.x;
    int p = bp % PP;
    int i = p / NN, j = p % NN;
    int tid = threadIdx.x;
    int w = tid >> 5, l = tid & 31;
    __shared__ float sA[8], sBq[8], sBk[8], sC[8];
    __shared__ float sc[NN][8];
    __shared__ float red1[8], red2[8];

    // per-head scalars: A = xq_h.xk_h, Bq = xq_h.bk_h, Bk = bq_h.xk_h, C = bq_h.bk_h
    {
        int idx = w * 32 + l;
        float xq = d_XQKV[(size_t)bp*768 + idx];
        float xk = d_XQKV[(size_t)bp*768 + 256 + idx];
        float bqv = bq0[idx], bkv = bk0[idx];
        float a = xq * xk, bqd = xq * bkv, bkd = bqv * xk, c = bqv * bkv;
#pragma unroll
        for (int o = 16; o > 0; o >>= 1) {
            a   += __shfl_xor_sync(~0u, a, o);
            bqd += __shfl_xor_sync(~0u, bqd, o);
            bkd += __shfl_xor_sync(~0u, bkd, o);
            c   += __shfl_xor_sync(~0u, c, o);
        }
        if (l == 0) { sA[w] = a; sBq[w] = bqd; sBk[w] = bkd; sC[w] = c; }
    }
    __syncthreads();

    // c[n,h] = sum_m softmax_m(score) * a_m over neighbors of n
    if (tid < NN * 8) {
        int n = tid >> 3, h = tid & 7;
        float A = sA[h], Bq = sBq[h], Bk = sBk[h], C = sC[h];
        float an = (float)((n == i) + (n == j));
        int dg = d_deg[n];
        float scm[4], amv[4];
        float mx = -1e30f;
        for (int s = 0; s < dg; s++) {
            int m = d_nbrs[n][s];
            float am = (float)((m == i) + (m == j));
            float sv = INV_SQRT_HD * (an*am*A + an*Bq + am*Bk + C);
            scm[s] = sv; amv[s] = am;
            mx = fmaxf(mx, sv);
        }
        float den = 0.f, num = 0.f;
        for (int s = 0; s < dg; s++) {
            float e = __expf(scm[s] - mx);
            den += e; num += e * amv[s];
        }
        sc[n][h] = num / den;
    }
    __syncthreads();

    // E2[n,d] = LN( cvec + a_n*x + sum_h c[n,h]*YV[h] )
    int d = tid;
    float xd = x[(size_t)bp*256 + d];
    float cv = d_cvec[d];
    float yv[8];
#pragma unroll
    for (int h = 0; h < 8; h++) yv[h] = d_YV[(size_t)bp*2048 + h*256 + d];
    float gd = g0[d], bd = b0[d];
    for (int n = 0; n < NN; n++) {
        float an = (float)((n == i) + (n == j));
        float v = cv + an * xd;
#pragma unroll
        for (int h = 0; h < 8; h++) v += sc[n][h] * yv[h];
        float s1 = v, s2 = v * v;
#pragma unroll
        for (int o = 16; o > 0; o >>= 1) {
            s1 += __shfl_xor_sync(~0u, s1, o);
            s2 += __shfl_xor_sync(~0u, s2, o);
        }
        __syncthreads();
        if (l == 0) { red1[w] = s1; red2[w] = s2; }
        __syncthreads();
        float mu = 0.f, m2 = 0.f;
#pragma unroll
        for (int q = 0; q < 8; q++) { mu += red1[q]; m2 += red2[q]; }
        mu *= (1.f/256.f); m2 *= (1.f/256.f);
        float rs = rsqrtf(m2 - mu*mu + LN_EPS);
        d_E2[((size_t)bp*NN + n)*256 + d] = (v - mu) * rs * gd + bd;
    }
}

// ---------------- layer-2 attention (sparse: 2 queries, <=4 keys each) ----------------
__global__ void __launch_bounds__(256) k_attn2() {
    int bp = blockIdx.x;
    int p = bp % PP;
    int tid = threadIdx.x;
    int w = tid >> 5, l = tid & 31;
    __shared__ float ssw[2][8][4];

    for (int task = w; task < 16; task += 8) {
        int t = task >> 3, h = task & 7;
        int dg = d_qdeg[p][t];
        float q = d_Q2[((size_t)bp*2 + t)*256 + h*32 + l];
        float scs[4];
        for (int s = 0; s < dg; s++) {
            int slot = d_qslot[p][t][s];
            float k = d_K2s[((size_t)bp*8 + slot)*256 + h*32 + l];
            float dt = q * k;
#pragma unroll
            for (int o = 16; o > 0; o >>= 1) dt += __shfl_xor_sync(~0u, dt, o);
            scs[s] = dt * INV_SQRT_HD;
        }
        if (l == 0) {
            float mx = -1e30f;
            for (int s = 0; s < dg; s++) mx = fmaxf(mx, scs[s]);
            float e[4]; float den = 0.f;
            for (int s = 0; s < dg; s++) { e[s] = __expf(scs[s] - mx); den += e[s]; }
            for (int s = 0; s < 4; s++) ssw[t][h][s] = (s < dg) ? e[s] / den : 0.f;
        }
    }
    __syncthreads();

    int d = tid, h = d >> 5;
    for (int t = 0; t < 2; t++) {
        int dg = d_qdeg[p][t];
        float acc = 0.f;
        for (int s = 0; s < dg; s++) {
            int slot = d_qslot[p][t][s];
            acc += ssw[t][h][s] * d_V2s[((size_t)bp*8 + slot)*256 + d];
        }
        d_ATT2[((size_t)bp*2 + t)*256 + d] = acc;
    }
}

// ---------------- final LN + readout ----------------
__global__ void __launch_bounds__(256) k_final(
    const float* __restrict__ x,
    const float* __restrict__ g1, const float* __restrict__ b1,
    float* __restrict__ out)
{
    int bp = blockIdx.x;
    int p = bp % PP;
    int i = p / NN, jn = p % NN;
    int tid = threadIdx.x, w = tid >> 5, l = tid & 31;
    __shared__ float red1[8], red2[8];
    int d = tid;
    float gd = g1[d], bd = b1[d];
    int nodes[2] = {i, jn};
    float e3[2];
    for (int t = 0; t < 2; t++) {
        float v = d_Z2[((size_t)bp*2 + t)*256 + d]
                + d_E2[((size_t)bp*NN + nodes[t])*256 + d];
        float s1 = v, s2 = v * v;
#pragma unroll
        for (int o = 16; o > 0; o >>= 1) {
            s1 += __shfl_xor_sync(~0u, s1, o);
            s2 += __shfl_xor_sync(~0u, s2, o);
        }
        __syncthreads();
        if (l == 0) { red1[w] = s1; red2[w] = s2; }
        __syncthreads();
        float mu = 0.f, m2 = 0.f;
#pragma unroll
        for (int q = 0; q < 8; q++) { mu += red1[q]; m2 += red2[q]; }
        mu *= (1.f/256.f); m2 *= (1.f/256.f);
        float rs = rsqrtf(m2 - mu*mu + LN_EPS);
        e3[t] = (v - mu) * rs * gd + bd;
    }
    out[(size_t)bp*256 + d] = 0.5f * (e3[0] + e3[1]) + x[(size_t)bp*256 + d];
}

// ---------------- launch ----------------
extern "C" void kernel_launch(void* const* d_in, const int* in_sizes, int n_in,
                              void* d_out, int out_size)
{
    const float* x   = (const float*)d_in[0];
    const float* adj = (const float*)d_in[1];
    const float* Wq  = (const float*)d_in[2];
    const float* bq  = (const float*)d_in[3];
    const float* Wk  = (const float*)d_in[4];
    const float* bk  = (const float*)d_in[5];
    const float* Wv  = (const float*)d_in[6];
    const float* bv  = (const float*)d_in[7];
    const float* Wo  = (const float*)d_in[8];
    const float* bo  = (const float*)d_in[9];
    const float* lg  = (const float*)d_in[10];
    const float* lb  = (const float*)d_in[11];
    float* out = (float*)d_out;

    float *XQKV, *YV, *E2, *Q2, *K2s, *V2s, *ATT2, *Z2;
    int *rowq, *rowm;
    cudaGetSymbolAddress((void**)&XQKV, d_XQKV);
    cudaGetSymbolAddress((void**)&YV,   d_YV);
    cudaGetSymbolAddress((void**)&E2,   d_E2);
    cudaGetSymbolAddress((void**)&Q2,   d_Q2);
    cudaGetSymbolAddress((void**)&K2s,  d_K2s);
    cudaGetSymbolAddress((void**)&V2s,  d_V2s);
    cudaGetSymbolAddress((void**)&ATT2, d_ATT2);
    cudaGetSymbolAddress((void**)&Z2,   d_Z2);
    cudaGetSymbolAddress((void**)&rowq, d_rowq);
    cudaGetSymbolAddress((void**)&rowm, d_rowm);

    k_tables<<<1, 384>>>(adj);
    k_rowmaps<<<(BPTOT + 255) / 256, 256>>>();
    k_cvec<<<1, 256>>>(bv, Wo, bo);

    dim3 g1((BPTOT + 127) / 128, 2);
    k_gemm<<<g1, 256>>>(x, 256, nullptr, Wq, nullptr, XQKV + 0,   768, BPTOT, 256);
    k_gemm<<<g1, 256>>>(x, 256, nullptr, Wk, nullptr, XQKV + 256, 768, BPTOT, 256);
    k_gemm<<<g1, 256>>>(x, 256, nullptr, Wv, nullptr, XQKV + 512, 768, BPTOT, 256);
    for (int h = 0; h < 8; h++)
        k_gemm<<<g1, 256>>>(XQKV + 512 + h*32, 768, nullptr, Wo + h*32*256, nullptr,
                            YV + h*256, 2048, BPTOT, 32);

    k_attn1<<<BPTOT, 256>>>(x, bq, bk, lg, lb);

    dim3 gq((BPTOT*2 + 127) / 128, 2), gm((BPTOT*8 + 127) / 128, 2);
    k_gemm<<<gq, 256>>>(E2, 256, rowq, Wq + 65536, bq + 256, Q2,  256, BPTOT*2, 256);
    k_gemm<<<gm, 256>>>(E2, 256, rowm, Wk + 65536, bk + 256, K2s, 256, BPTOT*8, 256);
    k_gemm<<<gm, 256>>>(E2, 256, rowm, Wv + 65536, bv + 256, V2s, 256, BPTOT*8, 256);

    k_attn2<<<BPTOT, 256>>>();

    k_gemm<<<gq, 256>>>(ATT2, 256, nullptr, Wo + 65536, bo + 256, Z2, 256, BPTOT*2, 256);

    k_final<<<BPTOT, 256>>>(x, lg + 256, lb + 256, out);
}

// round 4
// speedup vs baseline: 2.1444x; 2.1444x over previous
#include <cuda_runtime.h>

#define NN 19
#define PP 361
#define BB 16
#define HH 8
#define BPTOT (BB*PP)            // 5776
#define NQ (BPTOT*2)             // 11552
#define LN_EPS 1e-5f
#define INV_SQRT_HD 0.1767766952966369f   // 1/sqrt(32)

// ---------------- scratch: device globals ----------------
__device__ float d_XQKV[BPTOT*768];                   // [bp][xq|xk|xv]  (no bias)
__device__ float d_YV[(size_t)BPTOT*2048];            // [bp][h][256]
__device__ float d_E2[(size_t)BPTOT*NN*256];          // [bp][n][256] (only slist rows valid)
__device__ float d_Q2[(size_t)NQ*256];                // gathered queries (with bias)
__device__ float d_U[(size_t)NQ*2048];                // [row][h][256] = Wk_h^T q_h
__device__ float d_Zz[(size_t)NQ*2048];               // [row][h][256] = sum_m w*E2_m
__device__ float d_att[(size_t)NQ*256];
__device__ float d_Z2[(size_t)NQ*256];
__device__ float d_WkT[65536];                        // transpose of layer-2 Wk
__device__ float d_cvec[256];
__device__ int d_deg[NN];
__device__ int d_nbrs[NN][8];
__device__ int d_mlist[PP][8];                        // nbr(i) U nbr(j), padded
__device__ int d_qdeg[PP][2];
__device__ int d_qslot[PP][2][4];
__device__ int d_scnt[PP];
__device__ int d_slist[PP][12];                       // {i,j} U mlist
__device__ int d_rowq[NQ];

// ---------------- tables ----------------
__global__ void k_tables(const float* __restrict__ adj) {
    int t = threadIdx.x;
    if (t < NN) {
        int d = 0;
        for (int m = 0; m < NN; m++)
            if (adj[t*NN + m] > 0.f) d_nbrs[t][d++] = m;
        d_deg[t] = d;                 // max degree 4
    }
    __syncthreads();
    for (int p = t; p < PP; p += blockDim.x) {
        int i = p / NN, j = p % NN;
        int lst[8]; int cnt = 0;
        for (int s = 0; s < d_deg[i]; s++) lst[cnt++] = d_nbrs[i][s];
        for (int s = 0; s < d_deg[j]; s++) {
            int m = d_nbrs[j][s];
            bool f = false;
            for (int q = 0; q < cnt; q++) if (lst[q] == m) f = true;
            if (!f) lst[cnt++] = m;
        }
        for (int s = 0; s < 8; s++) d_mlist[p][s] = (s < cnt) ? lst[s] : lst[0];
        int nodes[2] = {i, j};
        for (int tt = 0; tt < 2; tt++) {
            int n = nodes[tt];
            int dg = d_deg[n];
            d_qdeg[p][tt] = dg;
            for (int s = 0; s < 4; s++) {
                int slot = 0;
                if (s < dg) {
                    int m = d_nbrs[n][s];
                    for (int q = 0; q < cnt; q++) if (lst[q] == m) { slot = q; break; }
                }
                d_qslot[p][tt][s] = slot;
            }
        }
        // slist = {i,j} U mlist (distinct)
        int sl[12]; int sc = 0;
        sl[sc++] = i;
        if (j != i) sl[sc++] = j;
        for (int s = 0; s < cnt; s++) {
            int m = lst[s];
            if (m != i && m != j) sl[sc++] = m;
        }
        d_scnt[p] = sc;
        for (int s = 0; s < 12; s++) d_slist[p][s] = (s < sc) ? sl[s] : sl[0];
    }
}

__global__ void k_rowmaps() {
    int bp = blockIdx.x * blockDim.x + threadIdx.x;
    if (bp >= BPTOT) return;
    int p = bp % PP;
    d_rowq[bp*2 + 0] = bp*NN + (p / NN);
    d_rowq[bp*2 + 1] = bp*NN + (p % NN);
}

// cvec = bv0 @ Wo0 + bo0
__global__ void k_cvec(const float* __restrict__ bv0, const float* __restrict__ Wo0,
                       const float* __restrict__ bo0) {
    int d = threadIdx.x;
    float acc = bo0[d];
    for (int k = 0; k < 256; k++) acc += bv0[k] * Wo0[k*256 + d];
    d_cvec[d] = acc;
}

// WkT[e][d] = Wk1[d][e]
__global__ void k_transpose(const float* __restrict__ Wk1) {
    int e = blockIdx.x, d = threadIdx.x;
    d_WkT[e*256 + d] = Wk1[d*256 + e];
}

// ---------------- GEMM core: 128x128 tile, K-chunk 16, 8x8 thread tiles ----------------
__device__ __forceinline__ void gemm_core128(
    const float* __restrict__ A, int lda, const int* __restrict__ rowmap,
    const float* __restrict__ B, const float* __restrict__ bias,
    float* __restrict__ C, int ldc, int M, int K, int row0, int col0)
{
    __shared__ float As[16][132];
    __shared__ float Bs[16][128];
    __shared__ int rmap[128];
    int tid = threadIdx.x;
    for (int r = tid; r < 128; r += 256) {
        int gi = row0 + r; if (gi > M-1) gi = M-1;
        rmap[r] = rowmap ? rowmap[gi] : gi;
    }
    __syncthreads();

    float acc[8][8];
#pragma unroll
    for (int i = 0; i < 8; i++)
#pragma unroll
        for (int j = 0; j < 8; j++) acc[i][j] = 0.f;

    int tx = tid & 15, ty = tid >> 4;
    int ar = tid & 127, akq = tid >> 7;          // A staging: row, k-quad (0/1)
    int bc = (tid & 31) * 4, bk = tid >> 5;      // B staging

    for (int k0 = 0; k0 < K; k0 += 16) {
        {
            const float* Ar = A + (size_t)rmap[ar] * lda + k0 + akq*4;
            float4 a0 = *(const float4*)Ar;
            float4 a1 = *(const float4*)(Ar + 8);
            int kb = akq*4;
            As[kb+0][ar] = a0.x; As[kb+1][ar] = a0.y;
            As[kb+2][ar] = a0.z; As[kb+3][ar] = a0.w;
            As[kb+8][ar] = a1.x; As[kb+9][ar] = a1.y;
            As[kb+10][ar] = a1.z; As[kb+11][ar] = a1.w;
        }
        {
            const float* Bp = B + (size_t)(k0 + bk)*256 + col0 + bc;
            float4 b0 = *(const float4*)Bp;
            float4 b1 = *(const float4*)(Bp + 8*256);
            *(float4*)&Bs[bk][bc]     = b0;
            *(float4*)&Bs[bk + 8][bc] = b1;
        }
        __syncthreads();
#pragma unroll
        for (int kk = 0; kk < 16; kk++) {
            float4 a01 = *(const float4*)&As[kk][ty*8];
            float4 a23 = *(const float4*)&As[kk][ty*8 + 4];
            float4 b01 = *(const float4*)&Bs[kk][tx*8];
            float4 b23 = *(const float4*)&Bs[kk][tx*8 + 4];
            float a[8] = {a01.x,a01.y,a01.z,a01.w,a23.x,a23.y,a23.z,a23.w};
            float b[8] = {b01.x,b01.y,b01.z,b01.w,b23.x,b23.y,b23.z,b23.w};
#pragma unroll
            for (int i = 0; i < 8; i++)
#pragma unroll
                for (int j = 0; j < 8; j++) acc[i][j] += a[i] * b[j];
        }
        __syncthreads();
    }

    float bi[8];
#pragma unroll
    for (int j = 0; j < 8; j++) bi[j] = bias ? __ldg(&bias[col0 + tx*8 + j]) : 0.f;
#pragma unroll
    for (int i = 0; i < 8; i++) {
        int gr = row0 + ty*8 + i;
        if (gr >= M) continue;
        float4 o0, o1;
        o0.x = acc[i][0]+bi[0]; o0.y = acc[i][1]+bi[1]; o0.z = acc[i][2]+bi[2]; o0.w = acc[i][3]+bi[3];
        o1.x = acc[i][4]+bi[4]; o1.y = acc[i][5]+bi[5]; o1.z = acc[i][6]+bi[6]; o1.w = acc[i][7]+bi[7];
        float* Cp = C + (size_t)gr*ldc + col0 + tx*8;
        *(float4*)Cp = o0;
        *(float4*)(Cp + 4) = o1;
    }
}

// wrappers
__global__ void __launch_bounds__(256,2) k_qkv(const float* __restrict__ x,
    const float* __restrict__ Wq, const float* __restrict__ Wk, const float* __restrict__ Wv) {
    const float* B = (blockIdx.z == 0) ? Wq : (blockIdx.z == 1 ? Wk : Wv);
    gemm_core128(x, 256, nullptr, B, nullptr, d_XQKV + blockIdx.z*256, 768,
                 BPTOT, 256, blockIdx.x*128, blockIdx.y*128);
}
__global__ void __launch_bounds__(256,2) k_yv(const float* __restrict__ Wo0) {
    int h = blockIdx.z;
    gemm_core128(d_XQKV + 512 + h*32, 768, nullptr, Wo0 + h*8192, nullptr,
                 d_YV + h*256, 2048, BPTOT, 32, blockIdx.x*128, blockIdx.y*128);
}
__global__ void __launch_bounds__(256,2) k_q2(const float* __restrict__ Wq1, const float* __restrict__ bq1) {
    gemm_core128(d_E2, 256, d_rowq, Wq1, bq1, d_Q2, 256,
                 NQ, 256, blockIdx.x*128, blockIdx.y*128);
}
__global__ void __launch_bounds__(256,2) k_u() {
    int h = blockIdx.z;
    gemm_core128(d_Q2 + h*32, 256, nullptr, d_WkT + h*32*256, nullptr,
                 d_U + h*256, 2048, NQ, 32, blockIdx.x*128, blockIdx.y*128);
}
__global__ void __launch_bounds__(256,2) k_z2(const float* __restrict__ Wo1, const float* __restrict__ bo1) {
    gemm_core128(d_att, 256, nullptr, Wo1, bo1, d_Z2, 256,
                 NQ, 256, blockIdx.x*128, blockIdx.y*128);
}

// ---------------- att GEMM: 256 rows x 32 cols per CTA, per-head ----------------
__global__ void __launch_bounds__(256,2) k_att(const float* __restrict__ Wv1,
                                               const float* __restrict__ bv1) {
    __shared__ float As[16][260];
    __shared__ float Bs[16][32];
    int h = blockIdx.y;
    int row0 = blockIdx.x * 256;
    int tid = threadIdx.x;
    int tx = tid & 7, ty = tid >> 3;

    float acc[8][4];
#pragma unroll
    for (int i = 0; i < 8; i++)
#pragma unroll
        for (int j = 0; j < 4; j++) acc[i][j] = 0.f;

    int arow = row0 + tid; if (arow > NQ-1) arow = NQ-1;
    const float* Arow = d_Zz + (size_t)arow*2048 + h*256;
    int bk = tid >> 4, bcc = (tid & 15) * 2;

    for (int k0 = 0; k0 < 256; k0 += 16) {
#pragma unroll
        for (int q = 0; q < 4; q++) {
            float4 v = *(const float4*)(Arow + k0 + q*4);
            As[q*4+0][tid] = v.x; As[q*4+1][tid] = v.y;
            As[q*4+2][tid] = v.z; As[q*4+3][tid] = v.w;
        }
        {
            float2 bv2 = *(const float2*)(Wv1 + (size_t)(k0 + bk)*256 + h*32 + bcc);
            Bs[bk][bcc] = bv2.x; Bs[bk][bcc+1] = bv2.y;
        }
        __syncthreads();
#pragma unroll
        for (int kk = 0; kk < 16; kk++) {
            float4 a01 = *(const float4*)&As[kk][ty*8];
            float4 a23 = *(const float4*)&As[kk][ty*8 + 4];
            float4 b4  = *(const float4*)&Bs[kk][tx*4];
            float a[8] = {a01.x,a01.y,a01.z,a01.w,a23.x,a23.y,a23.z,a23.w};
            float b[4] = {b4.x,b4.y,b4.z,b4.w};
#pragma unroll
            for (int i = 0; i < 8; i++)
#pragma unroll
                for (int j = 0; j < 4; j++) acc[i][j] += a[i] * b[j];
        }
        __syncthreads();
    }
    float bi[4];
#pragma unroll
    for (int j = 0; j < 4; j++) bi[j] = __ldg(&bv1[h*32 + tx*4 + j]);
#pragma unroll
    for (int i = 0; i < 8; i++) {
        int gr = row0 + ty*8 + i;
        if (gr >= NQ) continue;
        float4 o;
        o.x = acc[i][0]+bi[0]; o.y = acc[i][1]+bi[1]; o.z = acc[i][2]+bi[2]; o.w = acc[i][3]+bi[3];
        *(float4*)&d_att[(size_t)gr*256 + h*32 + tx*4] = o;
    }
}

// ---------------- layer-1 attention (collapsed) + E2 (slist only) + LN ----------------
__global__ void __launch_bounds__(256) k_attn1(
    const float* __restrict__ x,
    const float* __restrict__ bq0, const float* __restrict__ bk0,
    const float* __restrict__ g0, const float* __restrict__ b0)
{
    int bp = blockIdx.x;
    int p = bp % PP;
    int i = p / NN, j = p % NN;
    int tid = threadIdx.x;
    int w = tid >> 5, l = tid & 31;
    __shared__ float sA[8], sBq[8], sBk[8], sC[8];
    __shared__ float sc[NN][8];
    __shared__ float red1[8], red2[8];

    {
        int idx = w * 32 + l;
        float xq = d_XQKV[(size_t)bp*768 + idx];
        float xk = d_XQKV[(size_t)bp*768 + 256 + idx];
        float bqv = bq0[idx], bkv = bk0[idx];
        float a = xq * xk, bqd = xq * bkv, bkd = bqv * xk, c = bqv * bkv;
#pragma unroll
        for (int o = 16; o > 0; o >>= 1) {
            a   += __shfl_xor_sync(~0u, a, o);
            bqd += __shfl_xor_sync(~0u, bqd, o);
            bkd += __shfl_xor_sync(~0u, bkd, o);
            c   += __shfl_xor_sync(~0u, c, o);
        }
        if (l == 0) { sA[w] = a; sBq[w] = bqd; sBk[w] = bkd; sC[w] = c; }
    }
    __syncthreads();

    if (tid < NN * 8) {
        int n = tid >> 3, h = tid & 7;
        float A = sA[h], Bq = sBq[h], Bk = sBk[h], C = sC[h];
        float an = (float)((n == i) + (n == j));
        int dg = d_deg[n];
        float scm[4], amv[4];
        float mx = -1e30f;
        for (int s = 0; s < dg; s++) {
            int m = d_nbrs[n][s];
            float am = (float)((m == i) + (m == j));
            float sv = INV_SQRT_HD * (an*am*A + an*Bq + am*Bk + C);
            scm[s] = sv; amv[s] = am;
            mx = fmaxf(mx, sv);
        }
        float den = 0.f, num = 0.f;
        for (int s = 0; s < dg; s++) {
            float e = __expf(scm[s] - mx);
            den += e; num += e * amv[s];
        }
        sc[n][h] = num / den;
    }
    __syncthreads();

    int d = tid;
    float xd = x[(size_t)bp*256 + d];
    float cv = d_cvec[d];
    float yv[8];
#pragma unroll
    for (int h = 0; h < 8; h++) yv[h] = d_YV[(size_t)bp*2048 + h*256 + d];
    float gd = g0[d], bd = b0[d];
    int scn = d_scnt[p];
    for (int si = 0; si < scn; si++) {
        int n = d_slist[p][si];
        float an = (float)((n == i) + (n == j));
        float v = cv + an * xd;
#pragma unroll
        for (int h = 0; h < 8; h++) v += sc[n][h] * yv[h];
        float s1 = v, s2 = v * v;
#pragma unroll
        for (int o = 16; o > 0; o >>= 1) {
            s1 += __shfl_xor_sync(~0u, s1, o);
            s2 += __shfl_xor_sync(~0u, s2, o);
        }
        __syncthreads();
        if (l == 0) { red1[w] = s1; red2[w] = s2; }
        __syncthreads();
        float mu = 0.f, m2 = 0.f;
#pragma unroll
        for (int q = 0; q < 8; q++) { mu += red1[q]; m2 += red2[q]; }
        mu *= (1.f/256.f); m2 *= (1.f/256.f);
        float rs = rsqrtf(m2 - mu*mu + LN_EPS);
        d_E2[((size_t)bp*NN + n)*256 + d] = (v - mu) * rs * gd + bd;
    }
}

// ---------------- layer-2: scores via U, softmax, z = sum_m w*E2_m ----------------
__global__ void __launch_bounds__(256) k_score_z(const float* __restrict__ bk1) {
    int bp = blockIdx.x;
    int p = bp % PP;
    int tid = threadIdx.x;
    int w = tid >> 5, l = tid & 31;
    __shared__ float sEm[8][256];
    __shared__ float sw[2][8][4];

    // warp w loads E2 slot w
    {
        int m = d_mlist[p][w];
        const float* src = d_E2 + ((size_t)bp*NN + m)*256;
#pragma unroll
        for (int q = 0; q < 8; q++) sEm[w][q*32 + l] = src[q*32 + l];
    }
    __syncthreads();

    for (int task = w; task < 16; task += 8) {
        int t = task & 1, h = task >> 1;
        int row = bp*2 + t;
        float qv = d_Q2[(size_t)row*256 + h*32 + l];
        float qb = qv * bk1[h*32 + l];
#pragma unroll
        for (int o = 16; o > 0; o >>= 1) qb += __shfl_xor_sync(~0u, qb, o);
        float u[8];
        const float* Up = d_U + (size_t)row*2048 + h*256;
#pragma unroll
        for (int q = 0; q < 8; q++) u[q] = Up[q*32 + l];
        int dg = d_qdeg[p][t];
        float scs[4];
        for (int s = 0; s < dg; s++) {
            int slot = d_qslot[p][t][s];
            float dt = 0.f;
#pragma unroll
            for (int q = 0; q < 8; q++) dt += u[q] * sEm[slot][q*32 + l];
#pragma unroll
            for (int o = 16; o > 0; o >>= 1) dt += __shfl_xor_sync(~0u, dt, o);
            scs[s] = (dt + qb) * INV_SQRT_HD;
        }
        if (l == 0) {
            float mx = -1e30f;
            for (int s = 0; s < dg; s++) mx = fmaxf(mx, scs[s]);
            float e[4]; float den = 0.f;
            for (int s = 0; s < dg; s++) { e[s] = __expf(scs[s] - mx); den += e[s]; }
            for (int s = 0; s < 4; s++) sw[t][h][s] = (s < dg) ? e[s] / den : 0.f;
        }
    }
    __syncthreads();

    int d = tid;
#pragma unroll
    for (int t = 0; t < 2; t++) {
        int dg = d_qdeg[p][t];
        int sl[4]; float em[4];
#pragma unroll
        for (int s = 0; s < 4; s++) {
            sl[s] = d_qslot[p][t][s];
            em[s] = sEm[sl[s]][d];
        }
#pragma unroll
        for (int h = 0; h < 8; h++) {
            float acc = 0.f;
            for (int s = 0; s < dg; s++) acc += sw[t][h][s] * em[s];
            d_Zz[((size_t)(bp*2 + t)*8 + h)*256 + d] = acc;
        }
    }
}

// ---------------- final LN + readout ----------------
__global__ void __launch_bounds__(256) k_final(
    const float* __restrict__ x,
    const float* __restrict__ g1, const float* __restrict__ b1,
    float* __restrict__ out)
{
    int bp = blockIdx.x;
    int p = bp % PP;
    int i = p / NN, jn = p % NN;
    int tid = threadIdx.x, w = tid >> 5, l = tid & 31;
    __shared__ float red1[8], red2[8];
    int d = tid;
    float gd = g1[d], bd = b1[d];
    int nodes[2] = {i, jn};
    float e3[2];
    for (int t = 0; t < 2; t++) {
        float v = d_Z2[((size_t)bp*2 + t)*256 + d]
                + d_E2[((size_t)bp*NN + nodes[t])*256 + d];
        float s1 = v, s2 = v * v;
#pragma unroll
        for (int o = 16; o > 0; o >>= 1) {
            s1 += __shfl_xor_sync(~0u, s1, o);
            s2 += __shfl_xor_sync(~0u, s2, o);
        }
        __syncthreads();
        if (l == 0) { red1[w] = s1; red2[w] = s2; }
        __syncthreads();
        float mu = 0.f, m2 = 0.f;
#pragma unroll
        for (int q = 0; q < 8; q++) { mu += red1[q]; m2 += red2[q]; }
        mu *= (1.f/256.f); m2 *= (1.f/256.f);
        float rs = rsqrtf(m2 - mu*mu + LN_EPS);
        e3[t] = (v - mu) * rs * gd + bd;
    }
    out[(size_t)bp*256 + d] = 0.5f * (e3[0] + e3[1]) + x[(size_t)bp*256 + d];
}

// ---------------- launch ----------------
extern "C" void kernel_launch(void* const* d_in, const int* in_sizes, int n_in,
                              void* d_out, int out_size)
{
    const float* x   = (const float*)d_in[0];
    const float* adj = (const float*)d_in[1];
    const float* Wq  = (const float*)d_in[2];
    const float* bq  = (const float*)d_in[3];
    const float* Wk  = (const float*)d_in[4];
    const float* bk  = (const float*)d_in[5];
    const float* Wv  = (const float*)d_in[6];
    const float* bv  = (const float*)d_in[7];
    const float* Wo  = (const float*)d_in[8];
    const float* bo  = (const float*)d_in[9];
    const float* lg  = (const float*)d_in[10];
    const float* lb  = (const float*)d_in[11];
    float* out = (float*)d_out;

    k_tables<<<1, 384>>>(adj);
    k_rowmaps<<<(BPTOT + 255) / 256, 256>>>();
    k_cvec<<<1, 256>>>(bv, Wo, bo);
    k_transpose<<<256, 256>>>(Wk + 65536);

    k_qkv<<<dim3(46, 2, 3), 256>>>(x, Wq, Wk, Wv);
    k_yv<<<dim3(46, 2, 8), 256>>>(Wo);

    k_attn1<<<BPTOT, 256>>>(x, bq, bk, lg, lb);

    k_q2<<<dim3(91, 2), 256>>>(Wq + 65536, bq + 256);
    k_u<<<dim3(91, 2, 8), 256>>>();

    k_score_z<<<BPTOT, 256>>>(bk + 256);

    k_att<<<dim3(46, 8), 256>>>(Wv + 65536, bv + 256);
    k_z2<<<dim3(91, 2), 256>>>(Wo + 65536, bo + 256);

    k_final<<<BPTOT, 256>>>(x, lg + 256, lb + 256, out);
}

// round 5
// speedup vs baseline: 3.4601x; 1.6136x over previous
#include <cuda_runtime.h>

#define NN 19
#define PP 361
#define BB 16
#define HH 8
#define BPTOT (BB*PP)            // 5776
#define NQ (BPTOT*2)             // 11552
#define LN_EPS 1e-5f
#define INV_SQRT_HD 0.1767766952966369f   // 1/sqrt(32)

// ---------------- scratch: device globals ----------------
__device__ float d_XQKV[BPTOT*768];                   // [bp][xq|xk|xv]
__device__ float d_YV[(size_t)BPTOT*2048];            // [bp][h][256]
__device__ float d_E2[(size_t)BPTOT*NN*256];          // [bp][n][256] (slist rows valid)
__device__ float d_Q2[(size_t)NQ*256];
__device__ float d_U[(size_t)NQ*2048];                // [row][h][256] = Wk_h^T q_h
__device__ float d_Zz[(size_t)NQ*2048];               // [row][h][256] = sum_m w*E2_m
__device__ float d_att[(size_t)NQ*256];
__device__ float d_Z2[(size_t)NQ*256];
__device__ float d_WkT[65536];
__device__ float d_cvec[256];
__device__ int d_deg[NN];
__device__ int d_nbrs[NN][8];
__device__ int d_mlist[PP][8];
__device__ int d_qdeg[PP][2];
__device__ int d_qslot[PP][2][4];
__device__ int d_scnt[PP];
__device__ int d_slist[PP][12];
__device__ int d_rowq[NQ];

// ---------------- fused setup: pair tables + transpose + cvec ----------------
__global__ void __launch_bounds__(256) k_setup(
    const float* __restrict__ adj, const float* __restrict__ Wk1,
    const float* __restrict__ bv0, const float* __restrict__ Wo0,
    const float* __restrict__ bo0)
{
    int bid = blockIdx.x, t = threadIdx.x;
    if (bid < PP) {
        __shared__ int snbrs[NN][8];
        __shared__ int sdeg[NN];
        if (t < NN) {
            int d = 0;
            for (int m = 0; m < NN; m++)
                if (adj[t*NN + m] > 0.f) snbrs[t][d++] = m;
            sdeg[t] = d;                 // max degree 4
        }
        __syncthreads();
        int p = bid;
        int i = p / NN, j = p % NN;
        if (t == 0) {
            int lst[8]; int cnt = 0;
            for (int s = 0; s < sdeg[i]; s++) lst[cnt++] = snbrs[i][s];
            for (int s = 0; s < sdeg[j]; s++) {
                int m = snbrs[j][s];
                bool f = false;
                for (int q = 0; q < cnt; q++) if (lst[q] == m) f = true;
                if (!f) lst[cnt++] = m;
            }
            for (int s = 0; s < 8; s++) d_mlist[p][s] = (s < cnt) ? lst[s] : lst[0];
            int nodes2[2] = {i, j};
            for (int tt = 0; tt < 2; tt++) {
                int n = nodes2[tt], dg = sdeg[n];
                d_qdeg[p][tt] = dg;
                for (int s = 0; s < 4; s++) {
                    int slot = 0;
                    if (s < dg) {
                        int m = snbrs[n][s];
                        for (int q = 0; q < cnt; q++) if (lst[q] == m) { slot = q; break; }
                    }
                    d_qslot[p][tt][s] = slot;
                }
            }
            int sl[12]; int sc2 = 0;
            sl[sc2++] = i;
            if (j != i) sl[sc2++] = j;
            for (int s = 0; s < cnt; s++) {
                int m = lst[s];
                if (m != i && m != j) sl[sc2++] = m;
            }
            d_scnt[p] = sc2;
            for (int s = 0; s < 12; s++) d_slist[p][s] = (s < sc2) ? sl[s] : sl[0];
        }
        if (t < BB) {
            int bp = t * PP + p;
            d_rowq[bp*2 + 0] = bp*NN + i;
            d_rowq[bp*2 + 1] = bp*NN + j;
        }
        if (bid == 0 && t < NN) {
            d_deg[t] = sdeg[t];
            for (int s = 0; s < sdeg[t]; s++) d_nbrs[t][s] = snbrs[t][s];
        }
    } else if (bid < PP + 16) {
        int e0 = (bid - PP) * 16;
        for (int e = e0; e < e0 + 16; e++)
            d_WkT[e*256 + t] = Wk1[t*256 + e];
    } else {
        float acc = bo0[t];
        for (int k = 0; k < 256; k++) acc += bv0[k] * Wo0[k*256 + t];
        d_cvec[t] = acc;
    }
}

// ---------------- tf32 mma helpers ----------------
__device__ __forceinline__ unsigned f2tf(float x) {
    unsigned r; asm("cvt.rna.tf32.f32 %0, %1;" : "=r"(r) : "f"(x)); return r;
}
__device__ __forceinline__ void mma_tf32(float* c, const unsigned* a, const unsigned* b) {
    asm volatile("mma.sync.aligned.m16n8k8.row.col.f32.tf32.tf32.f32 "
        "{%0,%1,%2,%3}, {%4,%5,%6,%7}, {%8,%9}, {%0,%1,%2,%3};"
        : "+f"(c[0]), "+f"(c[1]), "+f"(c[2]), "+f"(c[3])
        : "r"(a[0]), "r"(a[1]), "r"(a[2]), "r"(a[3]), "r"(b[0]), "r"(b[1]));
}

// ---------------- wide tf32 GEMM core: 128x128 tile, K-chunk 32 ----------------
// C[M x 128cols@col0] = gather(A)[M,K] @ B[K, cols] (+bias)
__device__ __forceinline__ void mmt_core(
    const float* __restrict__ A, int lda, const int* __restrict__ rowmap,
    const float* __restrict__ B, int ldb, const float* __restrict__ bias,
    float* __restrict__ C, int ldc, int M, int K, int row0, int col0)
{
    __shared__ unsigned As[128][36];   // [m][k] pad 36 -> frag banks 4*gid+tig
    __shared__ unsigned Bs[32][136];   // [k][n] pad 136 -> frag banks 8*tig+n
    __shared__ int rmap[128];
    int tid = threadIdx.x;
    int lane = tid & 31, wid = tid >> 5;
    int wm = wid & 3, wn = wid >> 2;        // 4 x 2 warp grid
    int gid = lane >> 2, tig = lane & 3;

    for (int r = tid; r < 128; r += 256) {
        int gi = row0 + r; if (gi > M - 1) gi = M - 1;
        rmap[r] = rowmap ? rowmap[gi] : gi;
    }
    __syncthreads();

    float acc[2][8][4];
#pragma unroll
    for (int mi = 0; mi < 2; mi++)
#pragma unroll
        for (int ni = 0; ni < 8; ni++)
#pragma unroll
            for (int q = 0; q < 4; q++) acc[mi][ni][q] = 0.f;

    int sar = tid >> 1;                 // A staging row (0..127)
    int sak = (tid & 1) * 16;           // A staging k base
    const float* Abase = A + (size_t)rmap[sar] * lda + sak;
    int sbk = tid >> 3;                 // B staging k row (0..31)
    int sbn = (tid & 7) * 16;           // B staging n base

    for (int k0 = 0; k0 < K; k0 += 32) {
        if (k0) __syncthreads();
#pragma unroll
        for (int u = 0; u < 4; u++) {
            float4 v = *(const float4*)(Abase + k0 + u*4);
            uint4 w; w.x = f2tf(v.x); w.y = f2tf(v.y); w.z = f2tf(v.z); w.w = f2tf(v.w);
            *(uint4*)(&As[sar][sak + u*4]) = w;
        }
        const float* Bp = B + (size_t)(k0 + sbk) * ldb + col0 + sbn;
#pragma unroll
        for (int u = 0; u < 4; u++) {
            float4 v = *(const float4*)(Bp + u*4);
            uint4 w; w.x = f2tf(v.x); w.y = f2tf(v.y); w.z = f2tf(v.z); w.w = f2tf(v.w);
            *(uint4*)(&Bs[sbk][sbn + u*4]) = w;
        }
        __syncthreads();
#pragma unroll
        for (int ks = 0; ks < 4; ks++) {
            int kc0 = ks*8 + tig, kc1 = kc0 + 4;
            unsigned af[2][4], bf[8][2];
#pragma unroll
            for (int mi = 0; mi < 2; mi++) {
                int r0 = wm*32 + mi*16 + gid;
                af[mi][0] = As[r0][kc0];
                af[mi][1] = As[r0 + 8][kc0];
                af[mi][2] = As[r0][kc1];
                af[mi][3] = As[r0 + 8][kc1];
            }
#pragma unroll
            for (int ni = 0; ni < 8; ni++) {
                int n = wn*64 + ni*8 + gid;
                bf[ni][0] = Bs[kc0][n];
                bf[ni][1] = Bs[kc1][n];
            }
#pragma unroll
            for (int mi = 0; mi < 2; mi++)
#pragma unroll
                for (int ni = 0; ni < 8; ni++)
                    mma_tf32(acc[mi][ni], af[mi], bf[ni]);
        }
    }

#pragma unroll
    for (int mi = 0; mi < 2; mi++) {
#pragma unroll
        for (int half = 0; half < 2; half++) {
            int gr = row0 + wm*32 + mi*16 + gid + half*8;
            if (gr >= M) continue;
#pragma unroll
            for (int ni = 0; ni < 8; ni++) {
                int gc = col0 + wn*64 + ni*8 + tig*2;
                float v0 = acc[mi][ni][half*2 + 0];
                float v1 = acc[mi][ni][half*2 + 1];
                if (bias) { v0 += __ldg(&bias[gc]); v1 += __ldg(&bias[gc + 1]); }
                float2 o; o.x = v0; o.y = v1;
                *(float2*)&C[(size_t)gr * ldc + gc] = o;
            }
        }
    }
}

// wrappers
__global__ void __launch_bounds__(256) k_qkv(const float* __restrict__ x,
    const float* __restrict__ Wq, const float* __restrict__ Wk, const float* __restrict__ Wv) {
    const float* B = (blockIdx.z == 0) ? Wq : (blockIdx.z == 1 ? Wk : Wv);
    mmt_core(x, 256, nullptr, B, 256, nullptr, d_XQKV + blockIdx.z*256, 768,
             BPTOT, 256, blockIdx.x*128, blockIdx.y*128);
}
__global__ void __launch_bounds__(256) k_yv(const float* __restrict__ Wo0) {
    int h = blockIdx.z;
    mmt_core(d_XQKV + 512 + h*32, 768, nullptr, Wo0 + h*8192, 256, nullptr,
             d_YV + h*256, 2048, BPTOT, 32, blockIdx.x*128, blockIdx.y*128);
}
__global__ void __launch_bounds__(256) k_q2(const float* __restrict__ Wq1, const float* __restrict__ bq1) {
    mmt_core(d_E2, 256, d_rowq, Wq1, 256, bq1, d_Q2, 256,
             NQ, 256, blockIdx.x*128, blockIdx.y*128);
}
__global__ void __launch_bounds__(256) k_u() {
    int h = blockIdx.z;
    mmt_core(d_Q2 + h*32, 256, nullptr, d_WkT + h*32*256, 256, nullptr,
             d_U + h*256, 2048, NQ, 32, blockIdx.x*128, blockIdx.y*128);
}
__global__ void __launch_bounds__(256) k_z2(const float* __restrict__ Wo1, const float* __restrict__ bo1) {
    mmt_core(d_att, 256, nullptr, Wo1, 256, bo1, d_Z2, 256,
             NQ, 256, blockIdx.x*128, blockIdx.y*128);
}

// ---------------- narrow tf32 GEMM (N=32): att_h = Zz_h @ Wv_h + bv_h ----------------
__global__ void __launch_bounds__(256) k_att(const float* __restrict__ Wv1,
                                             const float* __restrict__ bv1) {
    __shared__ unsigned As[128][36];
    __shared__ unsigned Bs[32][40];
    int h = blockIdx.y;
    int row0 = blockIdx.x * 128;
    const float* A = d_Zz + h*256;       // lda 2048
    const float* B = Wv1 + h*32;         // ldb 256
    int tid = threadIdx.x, lane = tid & 31, wid = tid >> 5;
    int gid = lane >> 2, tig = lane & 3;

    float acc[4][4];
#pragma unroll
    for (int ni = 0; ni < 4; ni++)
#pragma unroll
        for (int q = 0; q < 4; q++) acc[ni][q] = 0.f;

    int sar = tid >> 1, sak = (tid & 1) * 16;
    int arow = row0 + sar; if (arow > NQ - 1) arow = NQ - 1;
    const float* Abase = A + (size_t)arow * 2048 + sak;
    int sbk = tid >> 3, sbc = (tid & 7) * 4;

    for (int k0 = 0; k0 < 256; k0 += 32) {
        if (k0) __syncthreads();
#pragma unroll
        for (int u = 0; u < 4; u++) {
            float4 v = *(const float4*)(Abase + k0 + u*4);
            uint4 w; w.x = f2tf(v.x); w.y = f2tf(v.y); w.z = f2tf(v.z); w.w = f2tf(v.w);
            *(uint4*)(&As[sar][sak + u*4]) = w;
        }
        {
            float4 v = *(const float4*)(B + (size_t)(k0 + sbk) * 256 + sbc);
            uint4 w; w.x = f2tf(v.x); w.y = f2tf(v.y); w.z = f2tf(v.z); w.w = f2tf(v.w);
            *(uint4*)(&Bs[sbk][sbc]) = w;
        }
        __syncthreads();
#pragma unroll
        for (int ks = 0; ks < 4; ks++) {
            int kc0 = ks*8 + tig, kc1 = kc0 + 4;
            int r0 = wid*16 + gid;
            unsigned af[4];
            af[0] = As[r0][kc0]; af[1] = As[r0 + 8][kc0];
            af[2] = As[r0][kc1]; af[3] = As[r0 + 8][kc1];
#pragma unroll
            for (int ni = 0; ni < 4; ni++) {
                unsigned bf[2];
                bf[0] = Bs[kc0][ni*8 + gid];
                bf[1] = Bs[kc1][ni*8 + gid];
                mma_tf32(acc[ni], af, bf);
            }
        }
    }
#pragma unroll
    for (int half = 0; half < 2; half++) {
        int gr = row0 + wid*16 + gid + half*8;
        if (gr >= NQ) continue;
#pragma unroll
        for (int ni = 0; ni < 4; ni++) {
            int gc = ni*8 + tig*2;
            float v0 = acc[ni][half*2 + 0] + __ldg(&bv1[h*32 + gc]);
            float v1 = acc[ni][half*2 + 1] + __ldg(&bv1[h*32 + gc + 1]);
            float2 o; o.x = v0; o.y = v1;
            *(float2*)&d_att[(size_t)gr*256 + h*32 + gc] = o;
        }
    }
}

// ---------------- layer-1 attention (collapsed) + E2 (slist only) + LN ----------------
__global__ void __launch_bounds__(256) k_attn1(
    const float* __restrict__ x,
    const float* __restrict__ bq0, const float* __restrict__ bk0,
    const float* __restrict__ g0, const float* __restrict__ b0)
{
    int bp = blockIdx.x;
    int p = bp % PP;
    int i = p / NN, j = p % NN;
    int tid = threadIdx.x;
    int w = tid >> 5, l = tid & 31;
    __shared__ float sA[8], sBq[8], sBk[8], sC[8];
    __shared__ float sc[NN][8];
    __shared__ float red1[8], red2[8];

    {
        int idx = w * 32 + l;
        float xq = d_XQKV[(size_t)bp*768 + idx];
        float xk = d_XQKV[(size_t)bp*768 + 256 + idx];
        float bqv = bq0[idx], bkv = bk0[idx];
        float a = xq * xk, bqd = xq * bkv, bkd = bqv * xk, c = bqv * bkv;
#pragma unroll
        for (int o = 16; o > 0; o >>= 1) {
            a   += __shfl_xor_sync(~0u, a, o);
            bqd += __shfl_xor_sync(~0u, bqd, o);
            bkd += __shfl_xor_sync(~0u, bkd, o);
            c   += __shfl_xor_sync(~0u, c, o);
        }
        if (l == 0) { sA[w] = a; sBq[w] = bqd; sBk[w] = bkd; sC[w] = c; }
    }
    __syncthreads();

    if (tid < NN * 8) {
        int n = tid >> 3, h = tid & 7;
        float A = sA[h], Bq = sBq[h], Bk = sBk[h], C = sC[h];
        float an = (float)((n == i) + (n == j));
        int dg = d_deg[n];
        float scm[4], amv[4];
        float mx = -1e30f;
        for (int s = 0; s < dg; s++) {
            int m = d_nbrs[n][s];
            float am = (float)((m == i) + (m == j));
            float sv = INV_SQRT_HD * (an*am*A + an*Bq + am*Bk + C);
            scm[s] = sv; amv[s] = am;
            mx = fmaxf(mx, sv);
        }
        float den = 0.f, num = 0.f;
        for (int s = 0; s < dg; s++) {
            float e = __expf(scm[s] - mx);
            den += e; num += e * amv[s];
        }
        sc[n][h] = num / den;
    }
    __syncthreads();

    int d = tid;
    float xd = x[(size_t)bp*256 + d];
    float cv = d_cvec[d];
    float yv[8];
#pragma unroll
    for (int h = 0; h < 8; h++) yv[h] = d_YV[(size_t)bp*2048 + h*256 + d];
    float gd = g0[d], bd = b0[d];
    int scn = d_scnt[p];
    for (int si = 0; si < scn; si++) {
        int n = d_slist[p][si];
        float an = (float)((n == i) + (n == j));
        float v = cv + an * xd;
#pragma unroll
        for (int h = 0; h < 8; h++) v += sc[n][h] * yv[h];
        float s1 = v, s2 = v * v;
#pragma unroll
        for (int o = 16; o > 0; o >>= 1) {
            s1 += __shfl_xor_sync(~0u, s1, o);
            s2 += __shfl_xor_sync(~0u, s2, o);
        }
        __syncthreads();
        if (l == 0) { red1[w] = s1; red2[w] = s2; }
        __syncthreads();
        float mu = 0.f, m2 = 0.f;
#pragma unroll
        for (int q = 0; q < 8; q++) { mu += red1[q]; m2 += red2[q]; }
        mu *= (1.f/256.f); m2 *= (1.f/256.f);
        float rs = rsqrtf(m2 - mu*mu + LN_EPS);
        d_E2[((size_t)bp*NN + n)*256 + d] = (v - mu) * rs * gd + bd;
    }
}

// ---------------- layer-2: scores via U, softmax, z = sum_m w*E2_m ----------------
__global__ void __launch_bounds__(256) k_score_z(const float* __restrict__ bk1) {
    int bp = blockIdx.x;
    int p = bp % PP;
    int tid = threadIdx.x;
    int w = tid >> 5, l = tid & 31;
    __shared__ float sEm[8][256];
    __shared__ float sw[2][8][4];

    {
        int m = d_mlist[p][w];
        const float* src = d_E2 + ((size_t)bp*NN + m)*256;
#pragma unroll
        for (int q = 0; q < 8; q++) sEm[w][q*32 + l] = src[q*32 + l];
    }
    __syncthreads();

    for (int task = w; task < 16; task += 8) {
        int t = task & 1, h = task >> 1;
        int row = bp*2 + t;
        float qv = d_Q2[(size_t)row*256 + h*32 + l];
        float qb = qv * bk1[h*32 + l];
#pragma unroll
        for (int o = 16; o > 0; o >>= 1) qb += __shfl_xor_sync(~0u, qb, o);
        float u[8];
        const float* Up = d_U + (size_t)row*2048 + h*256;
#pragma unroll
        for (int q = 0; q < 8; q++) u[q] = Up[q*32 + l];
        int dg = d_qdeg[p][t];
        float scs[4];
        for (int s = 0; s < dg; s++) {
            int slot = d_qslot[p][t][s];
            float dt = 0.f;
#pragma unroll
            for (int q = 0; q < 8; q++) dt += u[q] * sEm[slot][q*32 + l];
#pragma unroll
            for (int o = 16; o > 0; o >>= 1) dt += __shfl_xor_sync(~0u, dt, o);
            scs[s] = (dt + qb) * INV_SQRT_HD;
        }
        if (l == 0) {
            float mx = -1e30f;
            for (int s = 0; s < dg; s++) mx = fmaxf(mx, scs[s]);
            float e[4]; float den = 0.f;
            for (int s = 0; s < dg; s++) { e[s] = __expf(scs[s] - mx); den += e[s]; }
            for (int s = 0; s < 4; s++) sw[t][h][s] = (s < dg) ? e[s] / den : 0.f;
        }
    }
    __syncthreads();

    int d = tid;
#pragma unroll
    for (int t = 0; t < 2; t++) {
        int dg = d_qdeg[p][t];
        int sl[4]; float em[4];
#pragma unroll
        for (int s = 0; s < 4; s++) {
            sl[s] = d_qslot[p][t][s];
            em[s] = sEm[sl[s]][d];
        }
#pragma unroll
        for (int h = 0; h < 8; h++) {
            float acc = 0.f;
            for (int s = 0; s < dg; s++) acc += sw[t][h][s] * em[s];
            d_Zz[((size_t)(bp*2 + t)*8 + h)*256 + d] = acc;
        }
    }
}

// ---------------- final LN + readout ----------------
__global__ void __launch_bounds__(256) k_final(
    const float* __restrict__ x,
    const float* __restrict__ g1, const float* __restrict__ b1,
    float* __restrict__ out)
{
    int bp = blockIdx.x;
    int p = bp % PP;
    int i = p / NN, jn = p % NN;
    int tid = threadIdx.x, w = tid >> 5, l = tid & 31;
    __shared__ float red1[8], red2[8];
    int d = tid;
    float gd = g1[d], bd = b1[d];
    int nodes[2] = {i, jn};
    float e3[2];
    for (int t = 0; t < 2; t++) {
        float v = d_Z2[((size_t)bp*2 + t)*256 + d]
                + d_E2[((size_t)bp*NN + nodes[t])*256 + d];
        float s1 = v, s2 = v * v;
#pragma unroll
        for (int o = 16; o > 0; o >>= 1) {
            s1 += __shfl_xor_sync(~0u, s1, o);
            s2 += __shfl_xor_sync(~0u, s2, o);
        }
        __syncthreads();
        if (l == 0) { red1[w] = s1; red2[w] = s2; }
        __syncthreads();
        float mu = 0.f, m2 = 0.f;
#pragma unroll
        for (int q = 0; q < 8; q++) { mu += red1[q]; m2 += red2[q]; }
        mu *= (1.f/256.f); m2 *= (1.f/256.f);
        float rs = rsqrtf(m2 - mu*mu + LN_EPS);
        e3[t] = (v - mu) * rs * gd + bd;
    }
    out[(size_t)bp*256 + d] = 0.5f * (e3[0] + e3[1]) + x[(size_t)bp*256 + d];
}

// ---------------- launch ----------------
extern "C" void kernel_launch(void* const* d_in, const int* in_sizes, int n_in,
                              void* d_out, int out_size)
{
    const float* x   = (const float*)d_in[0];
    const float* adj = (const float*)d_in[1];
    const float* Wq  = (const float*)d_in[2];
    const float* bq  = (const float*)d_in[3];
    const float* Wk  = (const float*)d_in[4];
    const float* bk  = (const float*)d_in[5];
    const float* Wv  = (const float*)d_in[6];
    const float* bv  = (const float*)d_in[7];
    const float* Wo  = (const float*)d_in[8];
    const float* bo  = (const float*)d_in[9];
    const float* lg  = (const float*)d_in[10];
    const float* lb  = (const float*)d_in[11];
    float* out = (float*)d_out;

    k_setup<<<PP + 17, 256>>>(adj, Wk + 65536, bv, Wo, bo);

    k_qkv<<<dim3(46, 2, 3), 256>>>(x, Wq, Wk, Wv);
    k_yv<<<dim3(46, 2, 8), 256>>>(Wo);

    k_attn1<<<BPTOT, 256>>>(x, bq, bk, lg, lb);

    k_q2<<<dim3(91, 2), 256>>>(Wq + 65536, bq + 256);
    k_u<<<dim3(91, 2, 8), 256>>>();

    k_score_z<<<BPTOT, 256>>>(bk + 256);

    k_att<<<dim3(91, 8), 256>>>(Wv + 65536, bv + 256);
    k_z2<<<dim3(91, 2), 256>>>(Wo + 65536, bo + 256);

    k_final<<<BPTOT, 256>>>(x, lg + 256, lb + 256, out);
}